// round 17
// baseline (speedup 1.0000x reference)
#include <cuda_runtime.h>
#include <cuda_fp16.h>
#include <stdint.h>

// ---------------- problem constants ----------------
#define I_N 1024
#define O_N 36
#define C_N 1024
#define W_N 60
#define D_N 64
#define MARGIN 0.2f

#define IMG_PER_CTA 7
#define NCTA 147            // ceil(1024/7)
#define THREADS 512         // 16 warps; warp w owns m16-tile w (256 rows total)
#define CAP_BATCH 8         // captions per B buffer (8KB each, fp16)
#define NBATCH (C_N / CAP_BATCH)

// ---------------- smem layout (bytes from 1024-aligned base) ----------------
#define OFF_A    0          // 256 rows x 128B (fp16)            = 32768
#define OFF_B    32768      // 2 bufs x 64KB (8 captions each)   = 131072
#define OFF_RMAX 163840     // 2 bufs x 8 x 256 floats           = 16384
#define OFF_INV  180224     // 7 floats
#define SMEM_BYTES (180256 + 1024)

// ---------------- device globals ----------------
__device__ __half gA [(size_t)I_N * O_N * D_N];
__device__ __half gBh[(size_t)C_N * 64 * D_N];   // words padded to 64 w/ duplicate of last valid word
__device__ float g_scores[(size_t)I_N * C_N];
__device__ float g_diag[I_N];
__device__ float g_partial[I_N];
__device__ int   g_done = 0;    // last-block-done counter (reset by finalizer)

// ---------------- helpers ----------------
__device__ __forceinline__ uint32_t smem_u32(const void* p) {
    uint32_t a;
    asm("{ .reg .u64 t; cvta.to.shared.u64 t, %1; cvt.u32.u64 %0, t; }" : "=r"(a) : "l"(p));
    return a;
}
#define SW128(off) ((off) ^ (((off) >> 3) & 0x70))

__device__ __forceinline__ void ldsm4(uint32_t* r, uint32_t addr) {
    asm volatile("ldmatrix.sync.aligned.m8n8.x4.shared.b16 {%0,%1,%2,%3}, [%4];"
                 : "=r"(r[0]), "=r"(r[1]), "=r"(r[2]), "=r"(r[3]) : "r"(addr));
}
// fp16 inputs, fp16 accumulate: D/C are 2 packed f16x2 regs.
__device__ __forceinline__ void mma16816h(uint32_t* d, const uint32_t* a, const uint32_t* b) {
    asm volatile(
        "mma.sync.aligned.m16n8k16.row.col.f16.f16.f16.f16 "
        "{%0,%1}, {%2,%3,%4,%5}, {%6,%7}, {%0,%1};"
        : "+r"(d[0]), "+r"(d[1])
        : "r"(a[0]), "r"(a[1]), "r"(a[2]), "r"(a[3]), "r"(b[0]), "r"(b[1]));
}
__device__ __forceinline__ uint32_t hmax2u(uint32_t x, uint32_t y) {
    __half2 r = __hmax2(*reinterpret_cast<const __half2*>(&x),
                        *reinterpret_cast<const __half2*>(&y));
    return *reinterpret_cast<const uint32_t*>(&r);
}
#define CP16(dst, src) \
    asm volatile("cp.async.cg.shared.global [%0], [%1], 16;" :: "r"(dst), "l"(src))
#define CP_COMMIT()  asm volatile("cp.async.commit_group;" ::: "memory")
#define CP_WAIT(n)   asm volatile("cp.async.wait_group %0;" :: "n"(n) : "memory")

// ---------------- vectorized precompute: A + B convert/pad, 4 elems/thread ----
#define NA (I_N * O_N * D_N)
#define NB (C_N * 64 * D_N)
#define NA4 (NA / 4)
#define NB4 (NB / 4)

__device__ __forceinline__ uint2 cvt4(float4 v) {
    __half2 p0 = __floats2half2_rn(v.x, v.y);
    __half2 p1 = __floats2half2_rn(v.z, v.w);
    uint2 o;
    o.x = *reinterpret_cast<const uint32_t*>(&p0);
    o.y = *reinterpret_cast<const uint32_t*>(&p1);
    return o;
}

extern "C" __global__ void conv_kernel(const float* __restrict__ im,
                                       const float* __restrict__ s,
                                       const int* __restrict__ s_l)
{
    int idx = blockIdx.x * blockDim.x + threadIdx.x;
    if (idx < NA4) {
        float4 v = reinterpret_cast<const float4*>(im)[idx];
        reinterpret_cast<uint2*>(gA)[idx] = cvt4(v);
    } else if (idx < NA4 + NB4) {
        int g = idx - NA4;
        int d4 = g & 15;                 // 4-elem group within d (0..15)
        int w  = (g >> 4) & 63;          // padded word column
        int c  = g >> 10;                // caption
        int clen = s_l[c];
        // Pad words [clen, 64) with a COPY of word clen-1: max over any computed
        // superset of columns equals the true max -> no masking downstream.
        int ws = (w < clen) ? w : (clen - 1);
        float4 v = reinterpret_cast<const float4*>(
                       s + ((size_t)c * W_N + ws) * D_N)[d4];
        reinterpret_cast<uint2*>(gBh)[(c << 10) + (w << 4) + d4] = cvt4(v);
    }
}

// ---------------- main xattn-scores kernel ----------------
extern "C" __global__ void __launch_bounds__(THREADS, 1)
xattn_kernel(const int* __restrict__ im_l, const int* __restrict__ s_l)
{
    extern __shared__ char smraw[];
    const uint32_t raw_u = smem_u32(smraw);
    const uint32_t abase = (raw_u + 1023u) & ~1023u;
    char* base = smraw + (abase - raw_u);

    const int tid  = threadIdx.x;
    const int wid  = tid >> 5;          // 0..15, owns m16-tile wid
    const int lane = tid & 31;
    const int img0 = blockIdx.x * IMG_PER_CTA;
    const int n_img = (I_N - img0 < IMG_PER_CTA) ? (I_N - img0) : IMG_PER_CTA;

    float* rmaxb = (float*)(base + OFF_RMAX);  // [2][8][256]
    float* inv   = (float*)(base + OFF_INV);
    if (tid < n_img)
        inv[tid] = 1.0f / ((float)im_l[img0 + tid] + 1e-6f);

    // ---- stage A into swizzled smem; zero-pad rows >= n_img*36 ----
    {
        const int vchunks = n_img * O_N * 8;
        const uint4* ga = (const uint4*)(gA + (size_t)img0 * O_N * D_N);
        const uint4 z = make_uint4(0, 0, 0, 0);
        #pragma unroll
        for (int t = tid; t < 2048; t += THREADS) {
            uint32_t off = SW128((uint32_t)(t * 16));
            *(uint4*)(base + OFF_A + off) = (t < vchunks) ? ga[t] : z;
        }
    }

    // ---- prefetch B batch 0 (captions 0..7): 64 KB ----
    {
        const char* sh = (const char*)(gBh);
        uint32_t dst = abase + OFF_B;
        #pragma unroll
        for (int t = tid; t < 4096; t += THREADS) {
            uint32_t off = SW128((uint32_t)(t * 16));
            CP16(dst + off, sh + t * 16);
        }
    }
    CP_COMMIT();

    // ---- ldmatrix addressing invariants ----
    const uint32_t xr    = (uint32_t)((lane & 7) << 4);
    const uint32_t aColB = (uint32_t)((lane >> 4) << 4);
    const uint32_t aRow  = (uint32_t)(wid * 16 + (lane & 15));
    // B ldsm4: lane L -> row (L&7), matrix (L>>3); one x4 covers 2 k-steps.
    const uint32_t bRowOff = (uint32_t)((lane & 7) * 128);
    const uint32_t bMat    = (uint32_t)((lane >> 3) << 4);

    // epilogue mapping: quad q (0..55) -> (image q>>3, caption q&7)
    const int quad = tid >> 2;
    const int ql   = tid & 3;
    const int eimg = quad >> 3;
    const int ecap = quad & 7;
    const bool edo = (quad < 56) && (eimg < n_img);

    __syncthreads();   // A staged (needed before ldsm of A)

    // ---- A fragments resident in registers (one m-tile per warp) ----
    uint32_t af[4][4];
    #pragma unroll
    for (int k = 0; k < 4; ++k)
        ldsm4(af[k], abase + OFF_A + aRow * 128 + ((aColB + (uint32_t)(k * 32)) ^ xr));

    const uint32_t NEGINF2 = 0xFC00FC00u;   // packed {-inf, -inf} fp16

    for (int cc = 0; cc < NBATCH; ++cc) {
        // prefetch next batch (64 KB)
        if (cc + 1 < NBATCH) {
            const char* sh = (const char*)(gBh + (size_t)(cc + 1) * 32768);
            uint32_t dst = abase + OFF_B + (uint32_t)((cc + 1) & 1) * 65536;
            #pragma unroll
            for (int t = tid; t < 4096; t += THREADS) {
                uint32_t off = SW128((uint32_t)(t * 16));
                CP16(dst + off, sh + t * 16);
            }
            CP_COMMIT();
            CP_WAIT(1);
        } else {
            CP_WAIT(0);
        }
        // ONE barrier per batch: orders (a) B(cc) visibility for all warps,
        // (b) completeness of rmax(cc-1) writes, (c) WAR on rmax(cc) buffer.
        __syncthreads();

        // ---- deferred score epilogue for batch cc-1 (reads buf (cc-1)&1) ----
        if (cc > 0 && edo) {
            const float* rj = rmaxb + (uint32_t)((cc - 1) & 1) * 2048
                             + ecap * 256 + eimg * O_N;
            float v = 0.0f;
            #pragma unroll
            for (int i = 0; i < 9; ++i)
                v += rj[ql + 4 * i];
            v += __shfl_xor_sync(0xFFFFFFFFu, v, 1);
            v += __shfl_xor_sync(0xFFFFFFFFu, v, 2);
            if (ql == 0) {
                const int gc = CAP_BATCH * (cc - 1) + ecap;
                const int gr = img0 + eimg;
                float sc = v * inv[eimg];
                g_scores[(size_t)gr * C_N + gc] = sc;
                if (gr == gc) g_diag[gc] = sc;   // fused diag extraction
            }
        }

        // batch caption lengths: 2 vector LDGs (s_l offset is 32B-aligned)
        const int4 cl0 = *(const int4*)(s_l + CAP_BATCH * cc);
        const int4 cl1 = *(const int4*)(s_l + CAP_BATCH * cc + 4);
        const int clens[8] = { cl0.x, cl0.y, cl0.z, cl0.w,
                               cl1.x, cl1.y, cl1.z, cl1.w };

        float* rmax = rmaxb + (uint32_t)(cc & 1) * 2048;   // write buf cc&1

        #pragma unroll
        for (int j = 0; j < CAP_BATCH; ++j) {
            const int nlim = (clens[j] + 7) >> 3;  // n8 tiles to compute
            const uint32_t bh_base = abase + OFF_B + (uint32_t)((cc & 1) << 16)
                                    + (uint32_t)(j << 13);

            // packed column-pair maxes: mxp[0] = row r, mxp[1] = row r+8
            uint32_t mxp[2] = { NEGINF2, NEGINF2 };

            #pragma unroll
            for (int p = 0; p < 4; ++p) {
                const int n0 = 2 * p;
                if (n0 < nlim) {
                    const bool has2 = (n0 + 1) < nlim;
                    // bf[kp][0..3]: {r0,r1}=k-step 2kp, {r2,r3}=k-step 2kp+1
                    uint32_t bf0[2][4], bf1[2][4];
                    #pragma unroll
                    for (int kp = 0; kp < 2; ++kp)
                        ldsm4(bf0[kp], bh_base + (uint32_t)(n0 * 1024) + bRowOff
                                      + (((uint32_t)(kp * 64) + bMat) ^ xr));
                    if (has2) {
                        #pragma unroll
                        for (int kp = 0; kp < 2; ++kp)
                            ldsm4(bf1[kp], bh_base + (uint32_t)((n0 + 1) * 1024) + bRowOff
                                          + (((uint32_t)(kp * 64) + bMat) ^ xr));
                    }

                    uint32_t acc0[2] = { 0u, 0u };
                    uint32_t acc1[2] = { 0u, 0u };

                    #pragma unroll
                    for (int k = 0; k < 4; ++k) {
                        mma16816h(acc0, af[k], &bf0[k >> 1][(k & 1) * 2]);
                        if (has2)
                            mma16816h(acc1, af[k], &bf1[k >> 1][(k & 1) * 2]);
                    }

                    mxp[0] = hmax2u(mxp[0], acc0[0]);
                    mxp[1] = hmax2u(mxp[1], acc0[1]);
                    if (has2) {
                        mxp[0] = hmax2u(mxp[0], acc1[0]);
                        mxp[1] = hmax2u(mxp[1], acc1[1]);
                    }
                }
            }

            // unpack packed maxes -> float, fold halves, quad reduce
            float mx[2];
            {
                __half2 h0 = *reinterpret_cast<const __half2*>(&mxp[0]);
                __half2 h1 = *reinterpret_cast<const __half2*>(&mxp[1]);
                mx[0] = fmaxf(__low2float(h0), __high2float(h0));
                mx[1] = fmaxf(__low2float(h1), __high2float(h1));
            }
            #pragma unroll
            for (int q = 0; q < 2; ++q) {
                mx[q] = fmaxf(mx[q], __shfl_xor_sync(0xFFFFFFFFu, mx[q], 1));
                mx[q] = fmaxf(mx[q], __shfl_xor_sync(0xFFFFFFFFu, mx[q], 2));
            }
            if ((lane & 3) == 0) {
                float* rj = rmax + j * 256;
                const int row0 = wid * 16 + (lane >> 2);
                rj[row0]     = mx[0];
                rj[row0 + 8] = mx[1];
            }
        }
    }

    // ---- final batch's epilogue ----
    __syncthreads();
    if (edo) {
        const float* rj = rmaxb + (uint32_t)((NBATCH - 1) & 1) * 2048
                         + ecap * 256 + eimg * O_N;
        float v = 0.0f;
        #pragma unroll
        for (int i = 0; i < 9; ++i)
            v += rj[ql + 4 * i];
        v += __shfl_xor_sync(0xFFFFFFFFu, v, 1);
        v += __shfl_xor_sync(0xFFFFFFFFu, v, 2);
        if (ql == 0) {
            const int gc = CAP_BATCH * (NBATCH - 1) + ecap;
            const int gr = img0 + eimg;
            float sc = v * inv[eimg];
            g_scores[(size_t)gr * C_N + gc] = sc;
            if (gr == gc) g_diag[gc] = sc;
        }
    }
}

// ---------------- fused loss reduction (row partials + final sum) ----------
// Block b computes row b's hinge partial (fixed-order), then the LAST block
// to finish performs the final fixed-order sum over g_partial and writes out.
// The atomic only selects the finalizer; all arithmetic is in deterministic
// order, and the counter is reset to 0 for the next graph replay.
extern "C" __global__ void loss_kernel(float* out)
{
    const int b = blockIdx.x;
    const int tid = threadIdx.x;
    const float di = g_diag[b];
    float local = 0.0f;
    for (int c = tid; c < C_N; c += blockDim.x) {
        if (c == b) continue;
        float sc = g_scores[(size_t)b * C_N + c];
        local += fmaxf(0.0f, MARGIN + sc - di)
               + fmaxf(0.0f, MARGIN + sc - g_diag[c]);
    }
    __shared__ float buf[128];
    __shared__ int is_last;
    buf[tid] = local;
    __syncthreads();
    for (int s = 64; s > 0; s >>= 1) {
        if (tid < s) buf[tid] += buf[tid + s];
        __syncthreads();
    }
    if (tid == 0) {
        g_partial[b] = buf[0];
        __threadfence();
        int prev = atomicAdd(&g_done, 1);
        is_last = (prev == I_N - 1) ? 1 : 0;
    }
    __syncthreads();

    if (is_last) {
        // finalizer: fixed-order strided sum + tree reduce (deterministic)
        float v = 0.0f;
        for (int i = tid; i < I_N; i += 128) v += g_partial[i];
        buf[tid] = v;
        __syncthreads();
        for (int s = 64; s > 0; s >>= 1) {
            if (tid < s) buf[tid] += buf[tid + s];
            __syncthreads();
        }
        if (tid == 0) {
            out[0] = buf[0] * (1.0f / ((float)I_N * (float)C_N));
            g_done = 0;   // reset for next graph replay
        }
    }
}

// ---------------- launch ----------------
extern "C" void kernel_launch(void* const* d_in, const int* in_sizes, int n_in,
                              void* d_out, int out_size)
{
    const float* im   = (const float*)d_in[0];
    const float* s    = (const float*)d_in[1];
    const int*   im_l = (const int*)d_in[2];
    const int*   s_l  = (const int*)d_in[3];

    cudaFuncSetAttribute(xattn_kernel,
                         cudaFuncAttributeMaxDynamicSharedMemorySize, SMEM_BYTES);

    conv_kernel<<<(NA4 + NB4 + 255) / 256, 256>>>(im, s, s_l);
    xattn_kernel<<<NCTA, THREADS, SMEM_BYTES>>>(im_l, s_l);
    loss_kernel<<<I_N, 128>>>((float*)d_out);
}